// round 10
// baseline (speedup 1.0000x reference)
#include <cuda_runtime.h>
#include <cuda_fp16.h>
#include <math.h>
#include <stdint.h>

// Problem constants
#define NG   16
#define NIX  32
#define NIZ  32
#define NOUT 64
#define NB   512
#define NC   17
#define IJ   (NIX * NIZ)              // 1024
#define NBLK 148                      // persistent blocks (1/SM)
#define MAXT 7                        // ceil(1024/148)
#define SLAB_BYTES (NC * NC * NOUT * 2)   // 36992 (289 rows x 128B)
#define SLAB_CHUNKS (SLAB_BYTES / 16)     // 2312
#define OUTE (NOUT * NB)                  // 32768

// Repacked parameter tensor in fp16: P2h[cell][ij][o]  (o contiguous)
__device__ __half g_P2h[NC * NC * IJ * NOUT];
// Per-block partial outputs: 148 x 64 x 512 f32 = 19.4 MB
__device__ float g_part[NBLK * OUTE];

// ---------------------------------------------------------------------------
// Repack v2 (round-8 proven, ~16.5us = byte floor)
// ---------------------------------------------------------------------------
__global__ __launch_bounds__(256) void repack_kernel(const float* __restrict__ P) {
    __shared__ float tile[NOUT * 33];
    const int cell = blockIdx.x >> 5;
    const int ij0  = (blockIdx.x & 31) << 5;
    const int t    = threadIdx.x;

    const float* src = P     + cell * (NOUT * IJ) + ij0;
    __half*      dst = g_P2h + cell * (IJ * NOUT) + ij0 * NOUT;

#pragma unroll
    for (int p = 0; p < 2; ++p) {
        const int f = t + p * 256;
        const int o = f >> 3;
        const int c = f & 7;
        const float4 v = *reinterpret_cast<const float4*>(src + o * IJ + c * 4);
        float* tp = tile + o * 33 + c * 4;
        tp[0] = v.x; tp[1] = v.y; tp[2] = v.z; tp[3] = v.w;
    }
    __syncthreads();

    const int ij = t >> 3;
    const int og = t & 7;
    float v[8];
#pragma unroll
    for (int m = 0; m < 8; ++m)
        v[m] = tile[(og * 8 + m) * 33 + ij];
    __half2 h0 = __floats2half2_rn(v[0], v[1]);
    __half2 h1 = __floats2half2_rn(v[2], v[3]);
    __half2 h2 = __floats2half2_rn(v[4], v[5]);
    __half2 h3 = __floats2half2_rn(v[6], v[7]);
    uint4 q;
    q.x = *reinterpret_cast<unsigned*>(&h0);
    q.y = *reinterpret_cast<unsigned*>(&h1);
    q.z = *reinterpret_cast<unsigned*>(&h2);
    q.w = *reinterpret_cast<unsigned*>(&h3);
    *reinterpret_cast<uint4*>(dst + ij * NOUT + og * 8) = q;
}

// ---------------------------------------------------------------------------
// cp.async helpers
// ---------------------------------------------------------------------------
__device__ __forceinline__ uint32_t smem_u32(const void* p) {
    return (uint32_t)__cvta_generic_to_shared(p);
}
__device__ __forceinline__ void cp_async16(uint32_t saddr, const void* gptr) {
    asm volatile("cp.async.cg.shared.global [%0], [%1], 16;\n"
                 :: "r"(saddr), "l"(gptr) : "memory");
}
__device__ __forceinline__ void cp_commit() {
    asm volatile("cp.async.commit_group;\n" ::: "memory");
}
template <int N>
__device__ __forceinline__ void cp_wait() {
    asm volatile("cp.async.wait_group %0;\n" :: "n"(N) : "memory");
}

// Issue the 37 KB slab for one ij into an smem stage buffer (1024 threads).
__device__ __forceinline__ void issue_slab(char* dsm, int stage, int ij, int tid) {
    const uint32_t sbase = smem_u32(dsm) + stage * SLAB_BYTES;
    for (int c = tid; c < SLAB_CHUNKS; c += 1024) {
        const int line = c >> 3;            // cell 0..288
        const int sub  = c & 7;             // 16B sub-chunk within 128B row
        const __half* g = g_P2h + ((line * IJ + ij) * NOUT + sub * 8);
        cp_async16(sbase + c * 16, g);
    }
}

// Dynamic smem layout:
//   [0, 2*SLAB_BYTES)                          double-buffered slab (fp16)
//   [CELL_OFF, +MAXT*512*4)                    s_cell: corner00 byte offset
//   [W_OFF,    +MAXT*512*16)                   s_w: 4 f32 bilinear weights
// Epilogue reuses [0, 128KB) as float out[64][512].
#define CELL_OFF (2 * SLAB_BYTES)                       // 73984
#define W_OFF    (CELL_OFF + MAXT * NB * 4)             // 88320
#define SMEM_MAIN (W_OFF + MAXT * NB * 16)              // 145664

// ---------------------------------------------------------------------------
// Cell-major gather v2: 148 persistent blocks x 1024 threads; block handles
// ij = blk + 148t. Thread = (bgrp 0..63, og 0..15) owns 8 batches x 4 o-elems
// (acc[8][4] = 32 f32 regs -> no spill at the 64-reg/1024-thr cap).
// Inner loop: LDS.64 corners + cvt + f32 FFMA (proven-ILP pattern).
// ---------------------------------------------------------------------------
__global__ __launch_bounds__(1024, 1) void gather_kernel(
    const float* __restrict__ x,
    const float* __restrict__ z,
    const float* __restrict__ borders,
    const float* __restrict__ invlen)
{
    extern __shared__ char dsm[];
    const int blk = blockIdx.x;
    const int tid = threadIdx.x;
    const int nt  = (IJ - blk + NBLK - 1) / NBLK;   // 6 or 7

    int*    s_cell = reinterpret_cast<int*>(dsm + CELL_OFF);
    float4* s_w    = reinterpret_cast<float4*>(dsm + W_OFF);

    // Kick off slab 0 ASAP.
    issue_slab(dsm, 0, blk, tid);
    cp_commit();

    // Meta prologue: bins + f32 weights for this block's ij's (2 t's parallel).
    for (int t = tid >> 9; t < nt; t += 2) {
        const int b  = tid & 511;
        const int ij = blk + t * NBLK;
        const int i = ij >> 5;
        const int j = ij & 31;
        const float xv = x[i * NB + b];
        const float zv = z[j * NB + b];

        const float ex = expf(-fabsf(xv));
        const float cx = (xv > 0.0f) ? (1.0f - 0.5f * ex) : (0.5f * ex);
        int bx = (int)(cx * (float)NG); bx = max(0, min(NG - 1, bx));
        const float fx = (xv - borders[bx]) * invlen[bx];

        const float ez = expf(-fabsf(zv));
        const float cz = (zv > 0.0f) ? (1.0f - 0.5f * ez) : (0.5f * ez);
        int bz = (int)(cz * (float)NG); bz = max(0, min(NG - 1, bz));
        const float fz = (zv - borders[bz]) * invlen[bz];

        const float ax = 1.0f - fx;
        const float az = 1.0f - fz;
        s_w[t * NB + b]    = make_float4(ax * az, ax * fz, fx * az, fx * fz);
        s_cell[t * NB + b] = (bx * NC + bz) * 128;      // byte offset of row 00
    }

    const int og    = tid & 15;     // o-group: halfs [og*4, og*4+4)
    const int bgrp  = tid >> 4;     // 0..63; owns batches bgrp + 64k
    const int obyte = og * 8;

    float acc[8][4];
#pragma unroll
    for (int k = 0; k < 8; ++k)
#pragma unroll
        for (int e = 0; e < 4; ++e) acc[k][e] = 0.0f;

    for (int t = 0; t < nt; ++t) {
        if (t + 1 < nt) {
            issue_slab(dsm, (t + 1) & 1, blk + (t + 1) * NBLK, tid);
            cp_commit();
            cp_wait<1>();                 // slab t complete
        } else {
            cp_wait<0>();
        }
        __syncthreads();                  // slab t + meta visible to all

        const char*   slab = dsm + (t & 1) * SLAB_BYTES;
        const int*    cpm  = s_cell + t * NB;
        const float4* wpm  = s_w    + t * NB;

#pragma unroll
        for (int k = 0; k < 8; ++k) {
            const int b  = bgrp + (k << 6);
            const int co = cpm[b];               // 2 addrs/warp -> broadcast
            const float4 w = wpm[b];             // LDS.128, 2 addrs/warp
            const char* p = slab + co + obyte;

            const uint2 q00 = *reinterpret_cast<const uint2*>(p);
            const uint2 q01 = *reinterpret_cast<const uint2*>(p + 128);        // bz+1
            const uint2 q10 = *reinterpret_cast<const uint2*>(p + 17 * 128);   // bx+1
            const uint2 q11 = *reinterpret_cast<const uint2*>(p + 18 * 128);   // both

            const float2 a0 = __half22float2(*reinterpret_cast<const __half2*>(&q00.x));
            const float2 a1 = __half22float2(*reinterpret_cast<const __half2*>(&q00.y));
            const float2 b0 = __half22float2(*reinterpret_cast<const __half2*>(&q01.x));
            const float2 b1 = __half22float2(*reinterpret_cast<const __half2*>(&q01.y));
            const float2 c0 = __half22float2(*reinterpret_cast<const __half2*>(&q10.x));
            const float2 c1 = __half22float2(*reinterpret_cast<const __half2*>(&q10.y));
            const float2 d0 = __half22float2(*reinterpret_cast<const __half2*>(&q11.x));
            const float2 d1 = __half22float2(*reinterpret_cast<const __half2*>(&q11.y));

            acc[k][0] += w.x * a0.x; acc[k][1] += w.x * a0.y;
            acc[k][2] += w.x * a1.x; acc[k][3] += w.x * a1.y;
            acc[k][0] += w.y * b0.x; acc[k][1] += w.y * b0.y;
            acc[k][2] += w.y * b1.x; acc[k][3] += w.y * b1.y;
            acc[k][0] += w.z * c0.x; acc[k][1] += w.z * c0.y;
            acc[k][2] += w.z * c1.x; acc[k][3] += w.z * c1.y;
            acc[k][0] += w.w * d0.x; acc[k][1] += w.w * d0.y;
            acc[k][2] += w.w * d1.x; acc[k][3] += w.w * d1.y;
        }
        __syncthreads();   // protect stage buffer before next prefetch target
    }

    // Epilogue: stage partial in smem (reuse region), then vector copy out.
    float* s_out = reinterpret_cast<float*>(dsm);
#pragma unroll
    for (int k = 0; k < 8; ++k)
#pragma unroll
        for (int e = 0; e < 4; ++e)
            s_out[(og * 4 + e) * NB + bgrp + (k << 6)] = acc[k][e];
    __syncthreads();

    float4*       dst = reinterpret_cast<float4*>(g_part + blk * OUTE);
    const float4* src = reinterpret_cast<const float4*>(s_out);
    for (int c = tid; c < OUTE / 4; c += 1024)
        dst[c] = src[c];
}

// ---------------------------------------------------------------------------
// Reduce: out[e] = sum over 148 partials (19.4 MB read, ~3us).
// ---------------------------------------------------------------------------
__global__ __launch_bounds__(256) void reduce_kernel(float* __restrict__ out) {
    const int e = blockIdx.x * 256 + threadIdx.x;
    float a = 0.0f;
#pragma unroll 4
    for (int s = 0; s < NBLK; ++s)
        a += g_part[s * OUTE + e];
    out[e] = a;
}

// ---------------------------------------------------------------------------
extern "C" void kernel_launch(void* const* d_in, const int* in_sizes, int n_in,
                              void* d_out, int out_size) {
    const float* x       = (const float*)d_in[0];
    const float* z       = (const float*)d_in[1];
    const float* P       = (const float*)d_in[2];
    const float* borders = (const float*)d_in[3];
    const float* invlen  = (const float*)d_in[4];
    float* out = (float*)d_out;

    (void)in_sizes; (void)n_in; (void)out_size;

    static int smem_set = 0;
    if (!smem_set) {
        cudaFuncSetAttribute(gather_kernel,
                             cudaFuncAttributeMaxDynamicSharedMemorySize, SMEM_MAIN);
        smem_set = 1;
    }

    // Phase 1: repack P -> P2h (fp16, o contiguous), vectorized
    repack_kernel<<<NC * NC * 32, 256>>>(P);

    // Phase 2: cell-major gather, 148 persistent blocks x 1024 threads
    gather_kernel<<<NBLK, 1024, SMEM_MAIN>>>(x, z, borders, invlen);

    // Phase 3: reduce 148 partials
    reduce_kernel<<<OUTE / 256, 256>>>(out);
}

// round 11
// speedup vs baseline: 1.2168x; 1.2168x over previous
#include <cuda_runtime.h>
#include <cuda_fp16.h>
#include <math.h>
#include <stdint.h>

// Problem constants
#define NG   16          // NUM_GRIDS
#define NIX  32          // IN_X
#define NIZ  32          // IN_Z
#define NOUT 64          // OUT
#define NB   512         // BATCH
#define NC   17          // NUM_GRIDS + 1
#define IJ   (NIX * NIZ)         // 1024
#define JSTRH (IJ * NOUT)        // 65536 halfs: jj -> jj+1 step in P2h
#define ISTRH (NC * JSTRH)       // ii -> ii+1 step in P2h

// Repacked parameter tensor in fp16: P2h[cell][ij][o]  (o contiguous)
__device__ __half g_P2h[NC * NC * IJ * NOUT];

// ---------------------------------------------------------------------------
// cp.async helpers
// ---------------------------------------------------------------------------
__device__ __forceinline__ uint32_t smem_u32(const void* p) {
    return (uint32_t)__cvta_generic_to_shared(p);
}
__device__ __forceinline__ void cp_async16(uint32_t saddr, const void* gptr) {
    asm volatile("cp.async.cg.shared.global [%0], [%1], 16;\n"
                 :: "r"(saddr), "l"(gptr) : "memory");
}
__device__ __forceinline__ void cp_wait_all() {
    asm volatile("cp.async.wait_all;\n" ::: "memory");
}

// ---------------------------------------------------------------------------
// Repack v3: P[cell][o][ij] (fp32) -> P2h[cell][ij][o] (fp16).
// v2 was load-latency bound (issue 23.8%, DRAM 50.6%, MLP=2 blocking loads).
// v3 uses cp.async (async, no register scoreboard) for the tile fill.
// Tile pitch = 36 floats (144B): 16B-aligned rows for cp.async, and
// store-side column reads are broadcast/conflict-free (288 mod 32 == 0).
// ---------------------------------------------------------------------------
__global__ __launch_bounds__(256) void repack_kernel(const float* __restrict__ P) {
    __shared__ float tile[NOUT * 36];         // 9216 B
    const int cell = blockIdx.x >> 5;         // 0..288
    const int ij0  = (blockIdx.x & 31) << 5;  // 0..992
    const int t    = threadIdx.x;

    const float* src = P     + cell * (NOUT * IJ) + ij0;
    __half*      dst = g_P2h + cell * (IJ * NOUT) + ij0 * NOUT;

    // Async fill: 512 x 16B chunks (64 o-rows x 8 chunks) -> 2 per thread.
    const uint32_t tbase = smem_u32(tile);
#pragma unroll
    for (int p = 0; p < 2; ++p) {
        const int f = t + p * 256;
        const int o = f >> 3;                 // 0..63
        const int c = f & 7;                  // 0..7
        cp_async16(tbase + (o * 36 + c * 4) * 4, src + o * IJ + c * 4);
    }
    cp_wait_all();
    __syncthreads();

    // Store: 256 uint4 (32 ij x 8 o-groups) -> 1 per thread.
    const int ij = t >> 3;                    // 0..31
    const int og = t & 7;                     // 0..7
    float v[8];
#pragma unroll
    for (int m = 0; m < 8; ++m)
        v[m] = tile[(og * 8 + m) * 36 + ij];
    __half2 h0 = __floats2half2_rn(v[0], v[1]);
    __half2 h1 = __floats2half2_rn(v[2], v[3]);
    __half2 h2 = __floats2half2_rn(v[4], v[5]);
    __half2 h3 = __floats2half2_rn(v[6], v[7]);
    uint4 q;
    q.x = *reinterpret_cast<unsigned*>(&h0);
    q.y = *reinterpret_cast<unsigned*>(&h1);
    q.z = *reinterpret_cast<unsigned*>(&h2);
    q.w = *reinterpret_cast<unsigned*>(&h3);
    *reinterpret_cast<uint4*>(dst + ij * NOUT + og * 8) = q;
}

// ---------------------------------------------------------------------------
// fp16x8 weighted accumulate: acc[0..7] += w * (8 halfs in q).
// 8 independent f32 FFMA chains -- this instruction stream is the
// latency-hiding resource (proven rounds 6/9: cutting it regresses).
// ---------------------------------------------------------------------------
__device__ __forceinline__ void accum8(float acc[8], uint4 q, float w) {
    const __half2* h = reinterpret_cast<const __half2*>(&q);
#pragma unroll
    for (int m = 0; m < 4; ++m) {
        const float2 f = __half22float2(h[m]);
        acc[2 * m + 0] += w * f.x;
        acc[2 * m + 1] += w * f.y;
    }
}

// ---------------------------------------------------------------------------
// Gather (round-8 champion + unroll 8 + __expf): grid (NB), block 512, one
// batch per block; all blocks sweep the same ij order (cross-batch reuse).
// 8 lanes x 8 halfs cover the full 64-o row (128B lines).
// ---------------------------------------------------------------------------
__global__ __launch_bounds__(512) void gather_kernel(
    const float* __restrict__ x,
    const float* __restrict__ z,
    const float* __restrict__ borders,
    const float* __restrict__ invlen,
    float* __restrict__ out)
{
    const int b   = blockIdx.x;
    const int tid = threadIdx.x;

    __shared__ int   s_ix[NIX];
    __shared__ int   s_iz[NIZ];
    __shared__ float s_dx[NIX];
    __shared__ float s_dz[NIZ];

    // Per-batch index/weight precompute (laplace cdf binning)
    if (tid < 64) {
        const float v = (tid < 32) ? x[tid * NB + b] : z[(tid - 32) * NB + b];
        const float e = __expf(-fabsf(v));
        const float cdf = (v > 0.0f) ? (1.0f - 0.5f * e) : (0.5f * e);
        int idx = (int)(cdf * (float)NG);
        idx = max(0, min(NG - 1, idx));
        const float d = (v - borders[idx]) * invlen[idx];
        if (tid < 32) { s_ix[tid] = idx;      s_dx[tid] = d; }
        else          { s_iz[tid - 32] = idx; s_dz[tid - 32] = d; }
    }
    __syncthreads();

    const int og  = tid & 7;        // o-group: halfs [og*8, og*8+8) of 64
    const int ijg = tid >> 3;       // ij-group 0..63
    const int ooff = og * 8;

    float acc[8];
#pragma unroll
    for (int e = 0; e < 8; ++e) acc[e] = 0.0f;

#pragma unroll 8
    for (int k = 0; k < IJ / 64; ++k) {     // 16 sweep steps
        const int ij = ijg + (k << 6);
        const int i = ij >> 5;
        const int j = ij & 31;
        const int   ix = s_ix[i];
        const int   iz = s_iz[j];
        const float dx = s_dx[i];
        const float dz = s_dz[j];
        const float ax = 1.0f - dx;
        const float az = 1.0f - dz;
        const float w00 = ax * az;
        const float w01 = ax * dz;
        const float w10 = dx * az;
        const float w11 = dx * dz;

        const int base = ((ix * NC + iz) * IJ + ij) * NOUT + ooff;  // half units
        const __half* p = g_P2h + base;

        const uint4 q00 = *reinterpret_cast<const uint4*>(p);
        const uint4 q01 = *reinterpret_cast<const uint4*>(p + JSTRH);
        const uint4 q10 = *reinterpret_cast<const uint4*>(p + ISTRH);
        const uint4 q11 = *reinterpret_cast<const uint4*>(p + ISTRH + JSTRH);

        accum8(acc, q00, w00);
        accum8(acc, q01, w01);
        accum8(acc, q10, w10);
        accum8(acc, q11, w11);
    }

    // Warp reduction over the 4 ij-groups per warp (lane = (ijg&3)*8 + og)
#pragma unroll
    for (int m = 8; m <= 16; m <<= 1)
#pragma unroll
        for (int e = 0; e < 8; ++e)
            acc[e] += __shfl_xor_sync(0xffffffffu, acc[e], m);

    // Cross-warp reduction: 16 warps x 8 o-groups x 8 elems
    __shared__ float s_part[16][8][8];
    const int warp = tid >> 5;
    const int lane = tid & 31;
    if (lane < 8) {
#pragma unroll
        for (int e = 0; e < 8; ++e) s_part[warp][lane][e] = acc[e];
    }
    __syncthreads();

    if (tid < 64) {
        const int og2 = tid >> 3;       // o-group
        const int e   = tid & 7;        // element within group
        float a = s_part[0][og2][e];
#pragma unroll
        for (int w = 1; w < 16; ++w) a += s_part[w][og2][e];
        out[(og2 * 8 + e) * NB + b] = a;
    }
}

// ---------------------------------------------------------------------------
extern "C" void kernel_launch(void* const* d_in, const int* in_sizes, int n_in,
                              void* d_out, int out_size) {
    const float* x       = (const float*)d_in[0];  // (32, 512)
    const float* z       = (const float*)d_in[1];  // (32, 512)
    const float* P       = (const float*)d_in[2];  // (17,17,64,32,32)
    const float* borders = (const float*)d_in[3];  // (17,)
    const float* invlen  = (const float*)d_in[4];  // (16,)
    float* out = (float*)d_out;                    // (64, 512)

    (void)in_sizes; (void)n_in; (void)out_size;

    // Phase 1: repack P -> P2h (fp16, o contiguous), cp.async fill
    {
        repack_kernel<<<NC * NC * 32, 256>>>(P);   // 9248 blocks
    }

    // Phase 2: gather + accumulate (round-8 proven config, deeper unroll)
    {
        gather_kernel<<<NB, 512>>>(x, z, borders, invlen, out);
    }
}

// round 12
// speedup vs baseline: 1.4967x; 1.2300x over previous
#include <cuda_runtime.h>
#include <cuda_fp16.h>
#include <math.h>
#include <stdint.h>

// Problem constants
#define NG   16          // NUM_GRIDS
#define NIX  32          // IN_X
#define NIZ  32          // IN_Z
#define NOUT 64          // OUT
#define NB   512         // BATCH
#define NC   17          // NUM_GRIDS + 1
#define IJ   (NIX * NIZ)         // 1024
#define JSTRH (IJ * NOUT)        // 65536 halfs: jj -> jj+1 step in P2h
#define ISTRH (NC * JSTRH)       // ii -> ii+1 step in P2h

// Repacked parameter tensor in fp16: P2h[cell][ij][o]  (o contiguous)
__device__ __half g_P2h[NC * NC * IJ * NOUT];

// ---------------------------------------------------------------------------
// Repack v4: P[cell][o][ij] (fp32) -> P2h[cell][ij][o] (fp16).
// v2 structure (proven) with per-thread MLP doubled: tile 64 o x 64 ij,
// 4 float4 LDGs issued back-to-back into registers BEFORE any STS.
// Pitch 65 floats: store-phase column reads keep v2's benign 2-way conflict
// (8*65 mod 32 == 8 -> og lanes spread over banks {0,8,16,24} x2).
// ---------------------------------------------------------------------------
__global__ __launch_bounds__(256) void repack_kernel(const float* __restrict__ P) {
    __shared__ float tile[NOUT * 65];         // 16.6 KB
    const int cell = blockIdx.x >> 4;         // 0..288
    const int ij0  = (blockIdx.x & 15) << 6;  // 0..960
    const int t    = threadIdx.x;

    const float* src = P     + cell * (NOUT * IJ) + ij0;
    __half*      dst = g_P2h + cell * (IJ * NOUT) + ij0 * NOUT;

    // Load: 1024 float4 chunks (64 o-rows x 16 chunks of 64 ij) -> 4/thread,
    // all 4 LDGs in flight before the first smem store (MLP=4).
    float4 v4[4];
#pragma unroll
    for (int p = 0; p < 4; ++p) {
        const int f = t + p * 256;
        const int o = f >> 4;                 // 0..63
        const int c = f & 15;                 // 0..15
        v4[p] = *reinterpret_cast<const float4*>(src + o * IJ + c * 4);
    }
#pragma unroll
    for (int p = 0; p < 4; ++p) {
        const int f = t + p * 256;
        const int o = f >> 4;
        const int c = f & 15;
        float* tp = tile + o * 65 + c * 4;
        tp[0] = v4[p].x; tp[1] = v4[p].y; tp[2] = v4[p].z; tp[3] = v4[p].w;
    }
    __syncthreads();

    // Store: 512 uint4 (64 ij x 8 o-groups) -> 2 per thread.
#pragma unroll
    for (int p = 0; p < 2; ++p) {
        const int item = t + p * 256;
        const int ij = item >> 3;             // 0..63
        const int og = item & 7;              // 0..7
        float v[8];
#pragma unroll
        for (int m = 0; m < 8; ++m)
            v[m] = tile[(og * 8 + m) * 65 + ij];
        __half2 h0 = __floats2half2_rn(v[0], v[1]);
        __half2 h1 = __floats2half2_rn(v[2], v[3]);
        __half2 h2 = __floats2half2_rn(v[4], v[5]);
        __half2 h3 = __floats2half2_rn(v[6], v[7]);
        uint4 q;
        q.x = *reinterpret_cast<unsigned*>(&h0);
        q.y = *reinterpret_cast<unsigned*>(&h1);
        q.z = *reinterpret_cast<unsigned*>(&h2);
        q.w = *reinterpret_cast<unsigned*>(&h3);
        *reinterpret_cast<uint4*>(dst + ij * NOUT + og * 8) = q;
    }
}

// ---------------------------------------------------------------------------
// fp16x8 weighted accumulate: acc[0..7] += w * (8 halfs in q).
// 8 independent f32 FFMA chains -- this instruction stream is the
// latency-hiding resource (proven rounds 6/9: cutting it regresses).
// ---------------------------------------------------------------------------
__device__ __forceinline__ void accum8(float acc[8], uint4 q, float w) {
    const __half2* h = reinterpret_cast<const __half2*>(&q);
#pragma unroll
    for (int m = 0; m < 4; ++m) {
        const float2 f = __half22float2(h[m]);
        acc[2 * m + 0] += w * f.x;
        acc[2 * m + 1] += w * f.y;
    }
}

// ---------------------------------------------------------------------------
// Gather (round-11 measured best, 25.6us): grid (NB), block 512, one batch
// per block; all blocks sweep the same ij order (cross-batch reuse).
// 8 lanes x 8 halfs cover the full 64-o row (128B lines). BYTE-IDENTICAL
// to round 11 -- four restructuring attempts all regressed; equilibrium.
// ---------------------------------------------------------------------------
__global__ __launch_bounds__(512) void gather_kernel(
    const float* __restrict__ x,
    const float* __restrict__ z,
    const float* __restrict__ borders,
    const float* __restrict__ invlen,
    float* __restrict__ out)
{
    const int b   = blockIdx.x;
    const int tid = threadIdx.x;

    __shared__ int   s_ix[NIX];
    __shared__ int   s_iz[NIZ];
    __shared__ float s_dx[NIX];
    __shared__ float s_dz[NIZ];

    // Per-batch index/weight precompute (laplace cdf binning)
    if (tid < 64) {
        const float v = (tid < 32) ? x[tid * NB + b] : z[(tid - 32) * NB + b];
        const float e = __expf(-fabsf(v));
        const float cdf = (v > 0.0f) ? (1.0f - 0.5f * e) : (0.5f * e);
        int idx = (int)(cdf * (float)NG);
        idx = max(0, min(NG - 1, idx));
        const float d = (v - borders[idx]) * invlen[idx];
        if (tid < 32) { s_ix[tid] = idx;      s_dx[tid] = d; }
        else          { s_iz[tid - 32] = idx; s_dz[tid - 32] = d; }
    }
    __syncthreads();

    const int og  = tid & 7;        // o-group: halfs [og*8, og*8+8) of 64
    const int ijg = tid >> 3;       // ij-group 0..63
    const int ooff = og * 8;

    float acc[8];
#pragma unroll
    for (int e = 0; e < 8; ++e) acc[e] = 0.0f;

#pragma unroll 8
    for (int k = 0; k < IJ / 64; ++k) {     // 16 sweep steps
        const int ij = ijg + (k << 6);
        const int i = ij >> 5;
        const int j = ij & 31;
        const int   ix = s_ix[i];
        const int   iz = s_iz[j];
        const float dx = s_dx[i];
        const float dz = s_dz[j];
        const float ax = 1.0f - dx;
        const float az = 1.0f - dz;
        const float w00 = ax * az;
        const float w01 = ax * dz;
        const float w10 = dx * az;
        const float w11 = dx * dz;

        const int base = ((ix * NC + iz) * IJ + ij) * NOUT + ooff;  // half units
        const __half* p = g_P2h + base;

        const uint4 q00 = *reinterpret_cast<const uint4*>(p);
        const uint4 q01 = *reinterpret_cast<const uint4*>(p + JSTRH);
        const uint4 q10 = *reinterpret_cast<const uint4*>(p + ISTRH);
        const uint4 q11 = *reinterpret_cast<const uint4*>(p + ISTRH + JSTRH);

        accum8(acc, q00, w00);
        accum8(acc, q01, w01);
        accum8(acc, q10, w10);
        accum8(acc, q11, w11);
    }

    // Warp reduction over the 4 ij-groups per warp (lane = (ijg&3)*8 + og)
#pragma unroll
    for (int m = 8; m <= 16; m <<= 1)
#pragma unroll
        for (int e = 0; e < 8; ++e)
            acc[e] += __shfl_xor_sync(0xffffffffu, acc[e], m);

    // Cross-warp reduction: 16 warps x 8 o-groups x 8 elems
    __shared__ float s_part[16][8][8];
    const int warp = tid >> 5;
    const int lane = tid & 31;
    if (lane < 8) {
#pragma unroll
        for (int e = 0; e < 8; ++e) s_part[warp][lane][e] = acc[e];
    }
    __syncthreads();

    if (tid < 64) {
        const int og2 = tid >> 3;       // o-group
        const int e   = tid & 7;        // element within group
        float a = s_part[0][og2][e];
#pragma unroll
        for (int w = 1; w < 16; ++w) a += s_part[w][og2][e];
        out[(og2 * 8 + e) * NB + b] = a;
    }
}

// ---------------------------------------------------------------------------
extern "C" void kernel_launch(void* const* d_in, const int* in_sizes, int n_in,
                              void* d_out, int out_size) {
    const float* x       = (const float*)d_in[0];  // (32, 512)
    const float* z       = (const float*)d_in[1];  // (32, 512)
    const float* P       = (const float*)d_in[2];  // (17,17,64,32,32)
    const float* borders = (const float*)d_in[3];  // (17,)
    const float* invlen  = (const float*)d_in[4];  // (16,)
    float* out = (float*)d_out;                    // (64, 512)

    (void)in_sizes; (void)n_in; (void)out_size;

    // Phase 1: repack P -> P2h (fp16, o contiguous), MLP=4 loads
    {
        repack_kernel<<<NC * NC * 16, 256>>>(P);   // 4624 blocks
    }

    // Phase 2: gather + accumulate (round-11 proven config)
    {
        gather_kernel<<<NB, 512>>>(x, z, borders, invlen, out);
    }
}